// round 8
// baseline (speedup 1.0000x reference)
#include <cuda_runtime.h>
#include <cstdint>

// Gaussian 15x15 separable blur, 8192x8192 fp32, reflect pad, stride 1.
// Scanline streaming: cp.async 8-row groups, 32-row smem ring (4 slots),
// 3 groups in flight, ONE barrier per block. Horizontal conv 2 cols/thread
// (packed f32x2, symmetric), vertical via 16-slot f32x2 register ring.
// All smem / accumulator indices are compile-time immediates.

#define IMG_W 8192
#define IMG_H 8192
#define KS 15
#define HALO 7
#define TPB 128
#define TILE_W 256
#define TILE_H 128
#define NROWS (TILE_H + 2*HALO)     // 142 input rows per strip
#define ROW_F 272                   // floats per buffered row (x0-8 .. x0+263)
#define ROW_U (ROW_F/2)             // 136 ull per row
#define ROW_V4 68
#define RING 32
#define SMEM_BYTES (RING * ROW_F * 4)   // 34816 B

typedef unsigned long long ull;

static __device__ float g_k[KS];    // 1D Gaussian (kx == ky here)

__device__ __forceinline__ int reflect_idx(int p, int n) {
    p = (p < 0) ? -p : p;
    p = (p >= n) ? (2*n - 2 - p) : p;
    return p;
}
__device__ __forceinline__ ull pk2(float lo, float hi) {
    ull r; asm("mov.b64 %0, {%1, %2};" : "=l"(r) : "f"(lo), "f"(hi)); return r;
}
__device__ __forceinline__ void upk2(ull v, float& lo, float& hi) {
    asm("mov.b64 {%0, %1}, %2;" : "=f"(lo), "=f"(hi) : "l"(v));
}
__device__ __forceinline__ ull ffma2(ull a, ull b, ull c) {
    ull d; asm("fma.rn.f32x2 %0, %1, %2, %3;" : "=l"(d) : "l"(a), "l"(b), "l"(c)); return d;
}
__device__ __forceinline__ ull add2(ull a, ull b) {
    ull d; asm("add.rn.f32x2 %0, %1, %2;" : "=l"(d) : "l"(a), "l"(b)); return d;
}
__device__ __forceinline__ ull mul2(ull a, ull b) {
    ull d; asm("mul.rn.f32x2 %0, %1, %2;" : "=l"(d) : "l"(a), "l"(b)); return d;
}
__device__ __forceinline__ void cp16(uint32_t saddr, const float* g) {
    asm volatile("cp.async.cg.shared.global [%0], [%1], 16;"
                 :: "r"(saddr), "l"(g) : "memory");
}
#define CP_COMMIT() asm volatile("cp.async.commit_group;" ::: "memory")
#define CP_WAIT(N)  asm volatile("cp.async.wait_group %0;" :: "n"(N) : "memory")

// 1D kernel from the outer-product 2D kernel: row t sums to ky[t] (kx sums to 1).
__global__ void prep_kernel(const float* __restrict__ k2d) {
    int t = threadIdx.x;
    if (t < KS) {
        float s = 0.f;
#pragma unroll
        for (int i = 0; i < KS; i++) s += k2d[t * KS + i];
        g_k[t] = s;
    }
}

// One input row r (R32 = r & 31, compile-time): horizontal conv for this
// thread's 2 columns, vertical accumulate; optionally emit output row r-14.
template<int R32, int DMAX, bool EMIT>
__device__ __forceinline__ void rstep(const ull* __restrict__ wb,
                                      ull* acc, const ull* k2, float* op) {
    const ull* w = wb + R32 * ROW_U;      // immediate offset
    ull P[9]; float lo[9], hi[9];
#pragma unroll
    for (int c = 0; c < 9; c++) { P[c] = w[c]; upk2(P[c], lo[c], hi[c]); }
    // T_j = (raw[2p+1+j], raw[2p+2+j]), j = 0..14
    ull T[15];
#pragma unroll
    for (int i = 0; i < 8; i++) T[2*i] = pk2(hi[i], lo[i+1]);
#pragma unroll
    for (int i = 0; i < 7; i++) T[2*i+1] = P[i+1];
    // symmetric pairs, 4 independent chains + shallow add tree
    ull u0 = add2(T[0], T[14]);
    ull u1 = add2(T[1], T[13]);
    ull u2 = add2(T[2], T[12]);
    ull u3 = add2(T[3], T[11]);
    ull u4 = add2(T[4], T[10]);
    ull u5 = add2(T[5], T[9]);
    ull u6 = add2(T[6], T[8]);
    ull a0 = ffma2(k2[4], u4, mul2(k2[0], u0));
    ull a1 = ffma2(k2[5], u5, mul2(k2[1], u1));
    ull a2 = ffma2(k2[6], u6, mul2(k2[2], u2));
    ull a3 = ffma2(k2[7], T[7], mul2(k2[3], u3));
    ull h = add2(add2(a0, a1), add2(a2, a3));
    // vertical: row r feeds outputs t = r-d, d = 0..DMAX, coeff k[min(d,14-d)]
#pragma unroll
    for (int d = 0; d <= DMAX; d++) {
        const int s = ((R32 & 15) - d) & 15;
        const int ci = (d < 8) ? d : 14 - d;
        acc[s] = ffma2(k2[ci], h, acc[s]);
    }
    if (EMIT) {
        constexpr int st = ((R32 & 15) + 2) & 15;   // slot of output row r-14
        float e0, e1; upk2(acc[st], e0, e1);
        *(float2*)op = make_float2(e0, e1);
        acc[st] = 0ull;
    }
}

// Async prefetch of up to 8 rows [base, base+8) into the 32-row ring.
__device__ __forceinline__ void prefetch8(uint32_t ring_s, float* ring_g,
                                          const float* in, int x0, int y0,
                                          int base, bool xb, int tid) {
    if (base < NROWS) {
        int nr = NROWS - base; if (nr > 8) nr = 8;
        if (!xb) {
#pragma unroll 1
            for (int idx = tid; idx < nr * ROW_V4; idx += TPB) {
                int rr = idx / ROW_V4;
                int cc = idx - rr * ROW_V4;
                int r = base + rr;
                int gy = reflect_idx(y0 - HALO + r, IMG_H);
                const float* src = in + (size_t)gy * IMG_W + (x0 - 8 + 4 * cc);
                uint32_t dst = ring_s + (uint32_t)(((r & 31) * ROW_F + 4 * cc) * 4);
                cp16(dst, src);
            }
        } else {
#pragma unroll 1
            for (int rr = 0; rr < nr; rr++) {
                int r = base + rr;
                int gy = reflect_idx(y0 - HALO + r, IMG_H);
                const float* row = in + (size_t)gy * IMG_W;
                float* dst = ring_g + (r & 31) * ROW_F;
                for (int i = tid; i < ROW_F; i += TPB)
                    dst[i] = __ldg(row + reflect_idx(x0 - 8 + i, IMG_W));
            }
        }
    }
    CP_COMMIT();
}

extern __shared__ float ring[];

__global__ void __launch_bounds__(TPB, 6)
gauss_kernel(const float* __restrict__ in, float* __restrict__ out) {
    const int tid = threadIdx.x;
    const int x0 = blockIdx.x * TILE_W;
    const int y0 = blockIdx.y * TILE_H;
    const bool xb = (blockIdx.x == 0) || (blockIdx.x == gridDim.x - 1);
    const uint32_t ring_s = (uint32_t)__cvta_generic_to_shared(ring);
    const ull* wb = (const ull*)ring + tid;          // thread's first tap pair

    ull k2[8];
#pragma unroll
    for (int i = 0; i < 8; i++) { float a = g_k[i]; k2[i] = pk2(a, a); }
    ull acc[16];
#pragma unroll
    for (int i = 0; i < 16; i++) acc[i] = 0ull;

    float* outx = out + (size_t)y0 * IMG_W + x0 + 2 * tid;
    const size_t W = IMG_W;

    // Prime: 3 groups (blocks 0,1,2) in flight.
    prefetch8(ring_s, ring, in, x0, y0,  0, xb, tid);   // G0 rows 0..7
    prefetch8(ring_s, ring, in, x0, y0,  8, xb, tid);   // G1 rows 8..15
    prefetch8(ring_s, ring, in, x0, y0, 16, xb, tid);   // G2 rows 16..23

    // Per block b: wait oldest done + barrier (also proves block b-1 fully
    // consumed -> its ring slot is safe to overwrite), issue prefetch b+3,
    // then compute the 8 rows.
#define BLKTOP(B) CP_WAIT(2); __syncthreads(); \
    prefetch8(ring_s, ring, in, x0, y0, 8*((B)+3), xb, tid);

    // ---- block 0: rows 0..7 (warmup) ----
    BLKTOP(0)
    rstep<0,0,false>(wb, acc, k2, outx);
    rstep<1,1,false>(wb, acc, k2, outx);
    rstep<2,2,false>(wb, acc, k2, outx);
    rstep<3,3,false>(wb, acc, k2, outx);
    rstep<4,4,false>(wb, acc, k2, outx);
    rstep<5,5,false>(wb, acc, k2, outx);
    rstep<6,6,false>(wb, acc, k2, outx);
    rstep<7,7,false>(wb, acc, k2, outx);

    // ---- block 1: rows 8..15 (emit out 0,1) ----
    BLKTOP(1)
    rstep< 8, 8,false>(wb, acc, k2, outx);
    rstep< 9, 9,false>(wb, acc, k2, outx);
    rstep<10,10,false>(wb, acc, k2, outx);
    rstep<11,11,false>(wb, acc, k2, outx);
    rstep<12,12,false>(wb, acc, k2, outx);
    rstep<13,13,false>(wb, acc, k2, outx);
    rstep<14,14,true >(wb, acc, k2, outx + 0*W);
    rstep<15,14,true >(wb, acc, k2, outx + 1*W);

#define BLK8(P, ob) \
    rstep<(P)+0,14,true>(wb, acc, k2, (ob) + 0*W); \
    rstep<(P)+1,14,true>(wb, acc, k2, (ob) + 1*W); \
    rstep<(P)+2,14,true>(wb, acc, k2, (ob) + 2*W); \
    rstep<(P)+3,14,true>(wb, acc, k2, (ob) + 3*W); \
    rstep<(P)+4,14,true>(wb, acc, k2, (ob) + 4*W); \
    rstep<(P)+5,14,true>(wb, acc, k2, (ob) + 5*W); \
    rstep<(P)+6,14,true>(wb, acc, k2, (ob) + 6*W); \
    rstep<(P)+7,14,true>(wb, acc, k2, (ob) + 7*W);

    // ---- block 2: rows 16..23 -> out 2..9 ----
    BLKTOP(2)
    BLK8(16, outx + (size_t)2 * W)
    // ---- block 3: rows 24..31 -> out 10..17 ----
    BLKTOP(3)
    BLK8(24, outx + (size_t)10 * W)

    // ---- steady: superblocks s=0..2, blocks 4+4s .. 7+4s ----
#pragma unroll 1
    for (int s = 0; s < 3; s++) {
        const int b = 4 + 4*s;                 // phases 0,8,16,24
        float* ob = outx + (size_t)(8*b - 14) * W;
        BLKTOP(b+0)
        BLK8(0,  ob + (size_t)0 * W)
        BLKTOP(b+1)
        BLK8(8,  ob + (size_t)8 * W)
        BLKTOP(b+2)
        BLK8(16, ob + (size_t)16 * W)
        BLKTOP(b+3)
        BLK8(24, ob + (size_t)24 * W)
    }

    // ---- block 16: rows 128..135 -> out 114..121 ----
    BLKTOP(16)
    BLK8(0, outx + (size_t)114 * W)

    // ---- block 17 (tail): rows 136..141 -> out 122..127 ----
    CP_WAIT(0); __syncthreads();
    {
        float* ob = outx + (size_t)122 * W;
        rstep< 8,14,true>(wb, acc, k2, ob + 0*W);
        rstep< 9,14,true>(wb, acc, k2, ob + 1*W);
        rstep<10,14,true>(wb, acc, k2, ob + 2*W);
        rstep<11,14,true>(wb, acc, k2, ob + 3*W);
        rstep<12,14,true>(wb, acc, k2, ob + 4*W);
        rstep<13,14,true>(wb, acc, k2, ob + 5*W);
    }
}

extern "C" void kernel_launch(void* const* d_in, const int* in_sizes, int n_in,
                              void* d_out, int out_size) {
    const float* img = (const float*)d_in[0];   // [8192,8192] f32
    const float* ker = (const float*)d_in[1];   // [15,15] f32
    float* out = (float*)d_out;                 // [8192,8192] f32
    (void)in_sizes; (void)n_in; (void)out_size;

    prep_kernel<<<1, 32>>>(ker);

    dim3 grid(IMG_W / TILE_W, IMG_H / TILE_H);  // 32 x 64
    gauss_kernel<<<grid, TPB, SMEM_BYTES>>>(img, out);
}

// round 9
// speedup vs baseline: 1.2541x; 1.2541x over previous
#include <cuda_runtime.h>
#include <cstdint>

// Gaussian 15x15 separable blur, 8192x8192 fp32, reflect pad, stride 1.
// Scanline streaming (R4 schedule shape): cp.async 10-row groups into a
// 30-row smem ring, 2 groups in flight, prefetch issued BEFORE wait(1).
// Horizontal conv 2 cols/thread (packed f32x2, symmetric), vertical conv
// via 15-slot f32x2 register ring. All indices compile-time immediates.

#define IMG_W 8192
#define IMG_H 8192
#define KS 15
#define HALO 7
#define TPB 128
#define TILE_W 256
#define TILE_H 64
#define NROWS (TILE_H + 2*HALO)     // 78 input rows per strip
#define ROW_F 272                   // floats per buffered row (x0-8 .. x0+263)
#define ROW_U (ROW_F/2)             // 136 ull per row
#define ROW_V4 68
#define RING 30                     // rows in smem ring (3 x 10-row groups)
#define SMEM_BYTES (RING * ROW_F * 4)   // 32640 B -> 7 CTAs/SM

typedef unsigned long long ull;

static __device__ float g_k[KS];    // 1D Gaussian (kx == ky, sigma equal)

__device__ __forceinline__ int reflect_idx(int p, int n) {
    p = (p < 0) ? -p : p;
    p = (p >= n) ? (2*n - 2 - p) : p;
    return p;
}
__device__ __forceinline__ ull pk2(float lo, float hi) {
    ull r; asm("mov.b64 %0, {%1, %2};" : "=l"(r) : "f"(lo), "f"(hi)); return r;
}
__device__ __forceinline__ void upk2(ull v, float& lo, float& hi) {
    asm("mov.b64 {%0, %1}, %2;" : "=f"(lo), "=f"(hi) : "l"(v));
}
__device__ __forceinline__ ull ffma2(ull a, ull b, ull c) {
    ull d; asm("fma.rn.f32x2 %0, %1, %2, %3;" : "=l"(d) : "l"(a), "l"(b), "l"(c)); return d;
}
__device__ __forceinline__ ull add2(ull a, ull b) {
    ull d; asm("add.rn.f32x2 %0, %1, %2;" : "=l"(d) : "l"(a), "l"(b)); return d;
}
__device__ __forceinline__ ull mul2(ull a, ull b) {
    ull d; asm("mul.rn.f32x2 %0, %1, %2;" : "=l"(d) : "l"(a), "l"(b)); return d;
}
__device__ __forceinline__ void cp16(uint32_t saddr, const float* g) {
    asm volatile("cp.async.cg.shared.global [%0], [%1], 16;"
                 :: "r"(saddr), "l"(g) : "memory");
}
#define CP_COMMIT() asm volatile("cp.async.commit_group;" ::: "memory")
#define CP_WAIT(N)  asm volatile("cp.async.wait_group %0;" :: "n"(N) : "memory")

// 1D kernel from the outer-product 2D kernel: row t sums to ky[t].
__global__ void prep_kernel(const float* __restrict__ k2d) {
    int t = threadIdx.x;
    if (t < KS) {
        float s = 0.f;
#pragma unroll
        for (int i = 0; i < KS; i++) s += k2d[t * KS + i];
        g_k[t] = s;
    }
}

// One input row in ring slot SLOT (r mod 30) with AMOD = r mod 15:
// horizontal conv for this thread's 2 cols, vertical accumulate into the
// 15-slot acc ring; optionally emit output row r-14 (acc slot (AMOD+1)%15).
template<int SLOT, int AMOD, int DMAX, bool EMIT>
__device__ __forceinline__ void rstep(const ull* __restrict__ wb,
                                      ull* acc, const ull* k2, float* op) {
    const ull* w = wb + SLOT * ROW_U;     // immediate offset
    ull P[9]; float lo[9], hi[9];
#pragma unroll
    for (int c = 0; c < 9; c++) { P[c] = w[c]; upk2(P[c], lo[c], hi[c]); }
    ull T[15];
#pragma unroll
    for (int i = 0; i < 8; i++) T[2*i] = pk2(hi[i], lo[i+1]);
#pragma unroll
    for (int i = 0; i < 7; i++) T[2*i+1] = P[i+1];
    ull u0 = add2(T[0], T[14]);
    ull u1 = add2(T[1], T[13]);
    ull u2 = add2(T[2], T[12]);
    ull u3 = add2(T[3], T[11]);
    ull u4 = add2(T[4], T[10]);
    ull u5 = add2(T[5], T[9]);
    ull u6 = add2(T[6], T[8]);
    ull a0 = ffma2(k2[4], u4, mul2(k2[0], u0));
    ull a1 = ffma2(k2[5], u5, mul2(k2[1], u1));
    ull a2 = ffma2(k2[6], u6, mul2(k2[2], u2));
    ull a3 = ffma2(k2[7], T[7], mul2(k2[3], u3));
    ull h = add2(add2(a0, a1), add2(a2, a3));
#pragma unroll
    for (int d = 0; d <= DMAX; d++) {
        const int s = ((AMOD - d) % 15 + 15) % 15;
        const int ci = (d < 8) ? d : 14 - d;
        acc[s] = ffma2(k2[ci], h, acc[s]);
    }
    if (EMIT) {
        constexpr int st = (AMOD + 1) % 15;
        float e0, e1; upk2(acc[st], e0, e1);
        *(float2*)op = make_float2(e0, e1);
        acc[st] = 0ull;
    }
}

// Async prefetch of 10-row group at input row `base` into ring slots
// sbase..sbase+9 (compile-time constants at call sites). Always commits.
__device__ __forceinline__ void prefetch10(uint32_t ring_s, float* ring_g,
                                           const float* in, int x0, int y0,
                                           int base, int sbase,
                                           bool xb, int tid) {
    if (base < NROWS) {
        int nr = NROWS - base; if (nr > 10) nr = 10;
        if (!xb) {
#pragma unroll 1
            for (int idx = tid; idx < nr * ROW_V4; idx += TPB) {
                int rr = idx / ROW_V4;
                int cc = idx - rr * ROW_V4;
                int gy = reflect_idx(y0 - HALO + base + rr, IMG_H);
                const float* src = in + (size_t)gy * IMG_W + (x0 - 8 + 4 * cc);
                uint32_t dst = ring_s + (uint32_t)(((sbase + rr) * ROW_F + 4 * cc) * 4);
                cp16(dst, src);
            }
        } else {
#pragma unroll 1
            for (int rr = 0; rr < nr; rr++) {
                int gy = reflect_idx(y0 - HALO + base + rr, IMG_H);
                const float* row = in + (size_t)gy * IMG_W;
                float* dst = ring_g + (sbase + rr) * ROW_F;
                for (int i = tid; i < ROW_F; i += TPB)
                    dst[i] = __ldg(row + reflect_idx(x0 - 8 + i, IMG_W));
            }
        }
    }
    CP_COMMIT();
}

extern __shared__ float ring[];

__global__ void __launch_bounds__(TPB, 7)
gauss_kernel(const float* __restrict__ in, float* __restrict__ out) {
    const int tid = threadIdx.x;
    const int x0 = blockIdx.x * TILE_W;
    const int y0 = blockIdx.y * TILE_H;
    const bool xb = (blockIdx.x == 0) || (blockIdx.x == gridDim.x - 1);
    const uint32_t ring_s = (uint32_t)__cvta_generic_to_shared(ring);
    const ull* wb = (const ull*)ring + tid;          // thread's first tap pair

    ull k2[8];
#pragma unroll
    for (int i = 0; i < 8; i++) { float a = g_k[i]; k2[i] = pk2(a, a); }
    ull acc[15];
#pragma unroll
    for (int i = 0; i < 15; i++) acc[i] = 0ull;

    float* outx = out + (size_t)y0 * IMG_W + x0 + 2 * tid;
    const size_t W = IMG_W;

    // Prime two groups.
    prefetch10(ring_s, ring, in, x0, y0,  0,  0, xb, tid);   // g0
    prefetch10(ring_s, ring, in, x0, y0, 10, 10, xb, tid);   // g1

    // Per block b: issue g(b+2) (hidden under the wait), wait(1) -> g(b)
    // (and older) complete, sync, compute the 10 rows, end sync (protects
    // ring slots of group b before block b+1's prefetch overwrites them
    // ... which actually happens 3 blocks later; end sync keeps ordering).
#define BTOP(BASE, SB) \
    prefetch10(ring_s, ring, in, x0, y0, (BASE), (SB), xb, tid); \
    CP_WAIT(1); __syncthreads();
#define BEND __syncthreads();

#define PH0_FULL(ob) \
    rstep<0,0,14,true>(wb, acc, k2, (ob) + 0*W); \
    rstep<1,1,14,true>(wb, acc, k2, (ob) + 1*W); \
    rstep<2,2,14,true>(wb, acc, k2, (ob) + 2*W); \
    rstep<3,3,14,true>(wb, acc, k2, (ob) + 3*W); \
    rstep<4,4,14,true>(wb, acc, k2, (ob) + 4*W); \
    rstep<5,5,14,true>(wb, acc, k2, (ob) + 5*W); \
    rstep<6,6,14,true>(wb, acc, k2, (ob) + 6*W); \
    rstep<7,7,14,true>(wb, acc, k2, (ob) + 7*W); \
    rstep<8,8,14,true>(wb, acc, k2, (ob) + 8*W); \
    rstep<9,9,14,true>(wb, acc, k2, (ob) + 9*W);

#define PH1_FULL(ob) \
    rstep<10,10,14,true>(wb, acc, k2, (ob) + 0*W); \
    rstep<11,11,14,true>(wb, acc, k2, (ob) + 1*W); \
    rstep<12,12,14,true>(wb, acc, k2, (ob) + 2*W); \
    rstep<13,13,14,true>(wb, acc, k2, (ob) + 3*W); \
    rstep<14,14,14,true>(wb, acc, k2, (ob) + 4*W); \
    rstep<15, 0,14,true>(wb, acc, k2, (ob) + 5*W); \
    rstep<16, 1,14,true>(wb, acc, k2, (ob) + 6*W); \
    rstep<17, 2,14,true>(wb, acc, k2, (ob) + 7*W); \
    rstep<18, 3,14,true>(wb, acc, k2, (ob) + 8*W); \
    rstep<19, 4,14,true>(wb, acc, k2, (ob) + 9*W);

#define PH2_FULL(ob) \
    rstep<20, 5,14,true>(wb, acc, k2, (ob) + 0*W); \
    rstep<21, 6,14,true>(wb, acc, k2, (ob) + 1*W); \
    rstep<22, 7,14,true>(wb, acc, k2, (ob) + 2*W); \
    rstep<23, 8,14,true>(wb, acc, k2, (ob) + 3*W); \
    rstep<24, 9,14,true>(wb, acc, k2, (ob) + 4*W); \
    rstep<25,10,14,true>(wb, acc, k2, (ob) + 5*W); \
    rstep<26,11,14,true>(wb, acc, k2, (ob) + 6*W); \
    rstep<27,12,14,true>(wb, acc, k2, (ob) + 7*W); \
    rstep<28,13,14,true>(wb, acc, k2, (ob) + 8*W); \
    rstep<29,14,14,true>(wb, acc, k2, (ob) + 9*W);

    // ---- b0: rows 0..9 (warmup, partial DMAX) ----
    BTOP(20, 20)
    rstep<0,0,0,false>(wb, acc, k2, outx);
    rstep<1,1,1,false>(wb, acc, k2, outx);
    rstep<2,2,2,false>(wb, acc, k2, outx);
    rstep<3,3,3,false>(wb, acc, k2, outx);
    rstep<4,4,4,false>(wb, acc, k2, outx);
    rstep<5,5,5,false>(wb, acc, k2, outx);
    rstep<6,6,6,false>(wb, acc, k2, outx);
    rstep<7,7,7,false>(wb, acc, k2, outx);
    rstep<8,8,8,false>(wb, acc, k2, outx);
    rstep<9,9,9,false>(wb, acc, k2, outx);
    BEND

    // ---- b1: rows 10..19 (emit outs 0..5 from rows 14..19) ----
    BTOP(30, 0)
    rstep<10,10,10,false>(wb, acc, k2, outx);
    rstep<11,11,11,false>(wb, acc, k2, outx);
    rstep<12,12,12,false>(wb, acc, k2, outx);
    rstep<13,13,13,false>(wb, acc, k2, outx);
    rstep<14,14,14,true >(wb, acc, k2, outx + 0*W);
    rstep<15, 0,14,true >(wb, acc, k2, outx + 1*W);
    rstep<16, 1,14,true >(wb, acc, k2, outx + 2*W);
    rstep<17, 2,14,true >(wb, acc, k2, outx + 3*W);
    rstep<18, 3,14,true >(wb, acc, k2, outx + 4*W);
    rstep<19, 4,14,true >(wb, acc, k2, outx + 5*W);
    BEND

    // ---- b2: rows 20..29 -> outs 6..15 ----
    BTOP(40, 10)
    PH2_FULL(outx + (size_t)6 * W)
    BEND
    // ---- b3: rows 30..39 -> outs 16..25 ----
    BTOP(50, 20)
    PH0_FULL(outx + (size_t)16 * W)
    BEND
    // ---- b4: rows 40..49 -> outs 26..35 ----
    BTOP(60, 0)
    PH1_FULL(outx + (size_t)26 * W)
    BEND
    // ---- b5: rows 50..59 -> outs 36..45 ----
    BTOP(70, 10)
    PH2_FULL(outx + (size_t)36 * W)
    BEND
    // ---- b6: rows 60..69 -> outs 46..55 (prefetch beyond range: empty) ----
    BTOP(80, 20)
    PH0_FULL(outx + (size_t)46 * W)
    BEND
    // ---- b7: rows 70..77 -> outs 56..63 ----
    BTOP(90, 0)
    rstep<10,10,14,true>(wb, acc, k2, outx + (size_t)56 * W);
    rstep<11,11,14,true>(wb, acc, k2, outx + (size_t)57 * W);
    rstep<12,12,14,true>(wb, acc, k2, outx + (size_t)58 * W);
    rstep<13,13,14,true>(wb, acc, k2, outx + (size_t)59 * W);
    rstep<14,14,14,true>(wb, acc, k2, outx + (size_t)60 * W);
    rstep<15, 0,14,true>(wb, acc, k2, outx + (size_t)61 * W);
    rstep<16, 1,14,true>(wb, acc, k2, outx + (size_t)62 * W);
    rstep<17, 2,14,true>(wb, acc, k2, outx + (size_t)63 * W);
}

extern "C" void kernel_launch(void* const* d_in, const int* in_sizes, int n_in,
                              void* d_out, int out_size) {
    const float* img = (const float*)d_in[0];   // [8192,8192] f32
    const float* ker = (const float*)d_in[1];   // [15,15] f32
    float* out = (float*)d_out;                 // [8192,8192] f32
    (void)in_sizes; (void)n_in; (void)out_size;

    prep_kernel<<<1, 32>>>(ker);

    dim3 grid(IMG_W / TILE_W, IMG_H / TILE_H);  // 32 x 128
    gauss_kernel<<<grid, TPB, SMEM_BYTES>>>(img, out);
}

// round 10
// speedup vs baseline: 1.3150x; 1.0485x over previous
#include <cuda_runtime.h>
#include <cstdint>

// Gaussian 15x15 separable blur, 8192x8192 fp32, reflect pad, stride 1.
// R4 schedule (15-row cp.async groups, 2 in flight) + 30-row smem ring
// (7 CTAs/SM) + scalar-even horizontal decomposition (no packing MOVs):
//   odd taps  -> packed f32x2 on aligned smem pairs (symmetric)
//   even taps -> scalar symmetric sums on pair lanes (free extraction)
// Vertical conv via 15-slot f32x2 register accumulator ring.
// All smem-slot / acc-slot indices are compile-time immediates.

#define IMG_W 8192
#define IMG_H 8192
#define KS 15
#define HALO 7
#define TPB 128
#define TILE_W 256
#define TILE_H 64
#define NROWS (TILE_H + 2*HALO)     // 78 input rows per strip
#define ROW_F 272                   // floats per buffered row (x0-8 .. x0+263)
#define ROW_U (ROW_F/2)             // 136 ull per row
#define ROW_V4 68
#define RING 30                     // 2 x 15-row groups
#define SMEM_BYTES (RING * ROW_F * 4)   // 32640 B -> 7 CTAs/SM

typedef unsigned long long ull;

static __device__ float g_k[KS];    // 1D Gaussian (kx == ky, sigma equal)

__device__ __forceinline__ int reflect_idx(int p, int n) {
    p = (p < 0) ? -p : p;
    p = (p >= n) ? (2*n - 2 - p) : p;
    return p;
}
__device__ __forceinline__ ull pk2(float lo, float hi) {
    ull r; asm("mov.b64 %0, {%1, %2};" : "=l"(r) : "f"(lo), "f"(hi)); return r;
}
__device__ __forceinline__ void upk2(ull v, float& lo, float& hi) {
    asm("mov.b64 {%0, %1}, %2;" : "=f"(lo), "=f"(hi) : "l"(v));
}
__device__ __forceinline__ ull ffma2(ull a, ull b, ull c) {
    ull d; asm("fma.rn.f32x2 %0, %1, %2, %3;" : "=l"(d) : "l"(a), "l"(b), "l"(c)); return d;
}
__device__ __forceinline__ ull add2(ull a, ull b) {
    ull d; asm("add.rn.f32x2 %0, %1, %2;" : "=l"(d) : "l"(a), "l"(b)); return d;
}
__device__ __forceinline__ ull mul2(ull a, ull b) {
    ull d; asm("mul.rn.f32x2 %0, %1, %2;" : "=l"(d) : "l"(a), "l"(b)); return d;
}
__device__ __forceinline__ void cp16(uint32_t saddr, const float* g) {
    asm volatile("cp.async.cg.shared.global [%0], [%1], 16;"
                 :: "r"(saddr), "l"(g) : "memory");
}
#define CP_COMMIT() asm volatile("cp.async.commit_group;" ::: "memory")
#define CP_WAIT(N)  asm volatile("cp.async.wait_group %0;" :: "n"(N) : "memory")

// 1D kernel from the outer-product 2D kernel: row t sums to ky[t].
__global__ void prep_kernel(const float* __restrict__ k2d) {
    int t = threadIdx.x;
    if (t < KS) {
        float s = 0.f;
#pragma unroll
        for (int i = 0; i < KS; i++) s += k2d[t * KS + i];
        g_k[t] = s;
    }
}

// One input row in ring slot SLOT (compile-time), AMOD = r mod 15:
// horizontal conv for this thread's 2 cols, vertical accumulate into the
// 15-slot acc ring; optionally emit output row r-14.
//
// Thread t covers output cols (2t, 2t+1); buffer pairs P[c] = (buf[2t+2c],
// buf[2t+2c+1]).  y0 = sum_j k[j] buf[2t+1+j], y1 = sum_j k[j] buf[2t+2+j].
//   odd  j: packed — sum_odd k[j] * P[(j+1)/2]  (symmetric: P1+P7, P2+P6, P3+P5, P4)
//   even j: scalar — y0e over hi[0..7], y1e over lo[1..8] (symmetric quads)
template<int SLOT, int AMOD, int DMAX, bool EMIT>
__device__ __forceinline__ void rstep(const ull* __restrict__ wb,
                                      ull* acc, const ull* k2, float* op) {
    const ull* w = wb + SLOT * ROW_U;       // immediate offset
    ull P0 = w[0], P1 = w[1], P2 = w[2], P3 = w[3], P4 = w[4],
        P5 = w[5], P6 = w[6], P7 = w[7], P8 = w[8];
    float lo0, hi0, lo1, hi1, lo2, hi2, lo3, hi3, lo4, hi4,
          lo5, hi5, lo6, hi6, lo7, hi7, lo8, hi8;
    upk2(P0, lo0, hi0); upk2(P1, lo1, hi1); upk2(P2, lo2, hi2);
    upk2(P3, lo3, hi3); upk2(P4, lo4, hi4); upk2(P5, lo5, hi5);
    upk2(P6, lo6, hi6); upk2(P7, lo7, hi7); upk2(P8, lo8, hi8);

    // packed odd taps (coeffs k1,k3,k5,k7)
    ull s1 = add2(P1, P7);
    ull s2 = add2(P2, P6);
    ull s3 = add2(P3, P5);
    ull c1 = ffma2(k2[3], s2, mul2(k2[1], s1));
    ull c2 = ffma2(k2[5], s3, mul2(k2[7], P4));
    ull hod = add2(c1, c2);

    // scalar even taps (coeffs k0,k2,k4,k6) — lane extraction is free
    float k0s, k2s, k4s, k6s, dump;
    upk2(k2[0], k0s, dump); upk2(k2[2], k2s, dump);
    upk2(k2[4], k4s, dump); upk2(k2[6], k6s, dump);
    float t0 = hi0 + hi7, t1 = hi1 + hi6, t2 = hi2 + hi5, t3 = hi3 + hi4;
    float e0 = fmaf(k2s, t1, k0s * t0) + fmaf(k6s, t3, k4s * t2);
    float u0 = lo1 + lo8, u1 = lo2 + lo7, u2 = lo3 + lo6, u3 = lo4 + lo5;
    float e1 = fmaf(k2s, u1, k0s * u0) + fmaf(k6s, u3, k4s * u2);

    ull h = add2(hod, pk2(e0, e1));

    // vertical: row r feeds outputs t = r-d, d = 0..DMAX, coeff k[min(d,14-d)]
#pragma unroll
    for (int d = 0; d <= DMAX; d++) {
        const int s = ((AMOD - d) % 15 + 15) % 15;
        const int ci = (d < 8) ? d : 14 - d;
        acc[s] = ffma2(k2[ci], h, acc[s]);
    }
    if (EMIT) {
        constexpr int st = (AMOD + 1) % 15;     // slot of output row r-14
        float o0, o1; upk2(acc[st], o0, o1);
        *(float2*)op = make_float2(o0, o1);
        acc[st] = 0ull;
    }
}

// Async prefetch of a 15-row group at input row `base` into ring slots
// sbase..sbase+14 (sbase is 0 or 15 at call sites). Always commits.
__device__ __forceinline__ void prefetch15(uint32_t ring_s, float* ring_g,
                                           const float* in, int x0, int y0,
                                           int base, int sbase,
                                           bool xb, int tid) {
    if (base < NROWS) {
        int nr = NROWS - base; if (nr > 15) nr = 15;
        if (!xb) {
#pragma unroll 1
            for (int idx = tid; idx < nr * ROW_V4; idx += TPB) {
                int rr = idx / ROW_V4;
                int cc = idx - rr * ROW_V4;
                int gy = reflect_idx(y0 - HALO + base + rr, IMG_H);
                const float* src = in + (size_t)gy * IMG_W + (x0 - 8 + 4 * cc);
                uint32_t dst = ring_s + (uint32_t)(((sbase + rr) * ROW_F + 4 * cc) * 4);
                cp16(dst, src);
            }
        } else {
#pragma unroll 1
            for (int rr = 0; rr < nr; rr++) {
                int gy = reflect_idx(y0 - HALO + base + rr, IMG_H);
                const float* row = in + (size_t)gy * IMG_W;
                float* dst = ring_g + (sbase + rr) * ROW_F;
                for (int i = tid; i < ROW_F; i += TPB)
                    dst[i] = __ldg(row + reflect_idx(x0 - 8 + i, IMG_W));
            }
        }
    }
    CP_COMMIT();
}

extern __shared__ float ring[];

__global__ void __launch_bounds__(TPB, 7)
gauss_kernel(const float* __restrict__ in, float* __restrict__ out) {
    const int tid = threadIdx.x;
    const int x0 = blockIdx.x * TILE_W;
    const int y0 = blockIdx.y * TILE_H;
    const bool xb = (blockIdx.x == 0) || (blockIdx.x == gridDim.x - 1);
    const uint32_t ring_s = (uint32_t)__cvta_generic_to_shared(ring);
    const ull* wb = (const ull*)ring + tid;          // thread's first tap pair

    ull k2[8];
#pragma unroll
    for (int i = 0; i < 8; i++) { float a = g_k[i]; k2[i] = pk2(a, a); }
    ull acc[15];
#pragma unroll
    for (int i = 0; i < 15; i++) acc[i] = 0ull;

    float* outx = out + (size_t)y0 * IMG_W + x0 + 2 * tid;
    const size_t W = IMG_W;

    // Prime: groups g0 (rows 0-14 -> slots 0-14), g1 (rows 15-29 -> 15-29).
    prefetch15(ring_s, ring, in, x0, y0,  0,  0, xb, tid);
    prefetch15(ring_s, ring, in, x0, y0, 15, 15, xb, tid);

    // Full steady block: 15 rows at slot base SB (0 or 15), amod 0..14,
    // every row emits (output row = input row - 14).
#define PH(SB, ob) \
    rstep<(SB)+ 0, 0,14,true>(wb, acc, k2, (ob) +  0*W); \
    rstep<(SB)+ 1, 1,14,true>(wb, acc, k2, (ob) +  1*W); \
    rstep<(SB)+ 2, 2,14,true>(wb, acc, k2, (ob) +  2*W); \
    rstep<(SB)+ 3, 3,14,true>(wb, acc, k2, (ob) +  3*W); \
    rstep<(SB)+ 4, 4,14,true>(wb, acc, k2, (ob) +  4*W); \
    rstep<(SB)+ 5, 5,14,true>(wb, acc, k2, (ob) +  5*W); \
    rstep<(SB)+ 6, 6,14,true>(wb, acc, k2, (ob) +  6*W); \
    rstep<(SB)+ 7, 7,14,true>(wb, acc, k2, (ob) +  7*W); \
    rstep<(SB)+ 8, 8,14,true>(wb, acc, k2, (ob) +  8*W); \
    rstep<(SB)+ 9, 9,14,true>(wb, acc, k2, (ob) +  9*W); \
    rstep<(SB)+10,10,14,true>(wb, acc, k2, (ob) + 10*W); \
    rstep<(SB)+11,11,14,true>(wb, acc, k2, (ob) + 11*W); \
    rstep<(SB)+12,12,14,true>(wb, acc, k2, (ob) + 12*W); \
    rstep<(SB)+13,13,14,true>(wb, acc, k2, (ob) + 13*W); \
    rstep<(SB)+14,14,14,true>(wb, acc, k2, (ob) + 14*W);

    // ---- B0: rows 0..14 (warmup; row 14 emits output 0) ----
    CP_WAIT(1); __syncthreads();
    rstep< 0, 0, 0,false>(wb, acc, k2, outx);
    rstep< 1, 1, 1,false>(wb, acc, k2, outx);
    rstep< 2, 2, 2,false>(wb, acc, k2, outx);
    rstep< 3, 3, 3,false>(wb, acc, k2, outx);
    rstep< 4, 4, 4,false>(wb, acc, k2, outx);
    rstep< 5, 5, 5,false>(wb, acc, k2, outx);
    rstep< 6, 6, 6,false>(wb, acc, k2, outx);
    rstep< 7, 7, 7,false>(wb, acc, k2, outx);
    rstep< 8, 8, 8,false>(wb, acc, k2, outx);
    rstep< 9, 9, 9,false>(wb, acc, k2, outx);
    rstep<10,10,10,false>(wb, acc, k2, outx);
    rstep<11,11,11,false>(wb, acc, k2, outx);
    rstep<12,12,12,false>(wb, acc, k2, outx);
    rstep<13,13,13,false>(wb, acc, k2, outx);
    rstep<14,14,14,true >(wb, acc, k2, outx);      // output row 0
    __syncthreads();
    prefetch15(ring_s, ring, in, x0, y0, 30,  0, xb, tid);   // g2 -> slots 0-14

    // ---- B1: rows 15..29 -> outputs 1..15 ----
    CP_WAIT(1); __syncthreads();
    PH(15, outx + (size_t)1 * W)
    __syncthreads();
    prefetch15(ring_s, ring, in, x0, y0, 45, 15, xb, tid);   // g3 -> slots 15-29

    // ---- B2: rows 30..44 -> outputs 16..30 ----
    CP_WAIT(1); __syncthreads();
    PH(0, outx + (size_t)16 * W)
    __syncthreads();
    prefetch15(ring_s, ring, in, x0, y0, 60,  0, xb, tid);   // g4 -> slots 0-14

    // ---- B3: rows 45..59 -> outputs 31..45 ----
    CP_WAIT(1); __syncthreads();
    PH(15, outx + (size_t)31 * W)
    __syncthreads();
    prefetch15(ring_s, ring, in, x0, y0, 75, 15, xb, tid);   // g5 (3 rows) -> 15-17

    // ---- B4: rows 60..74 -> outputs 46..60 ----
    CP_WAIT(1); __syncthreads();
    PH(0, outx + (size_t)46 * W)
    __syncthreads();

    // ---- B5: rows 75..77 -> outputs 61..63 ----
    CP_WAIT(0); __syncthreads();
    rstep<15, 0,14,true>(wb, acc, k2, outx + (size_t)61 * W);
    rstep<16, 1,14,true>(wb, acc, k2, outx + (size_t)62 * W);
    rstep<17, 2,14,true>(wb, acc, k2, outx + (size_t)63 * W);
}

extern "C" void kernel_launch(void* const* d_in, const int* in_sizes, int n_in,
                              void* d_out, int out_size) {
    const float* img = (const float*)d_in[0];   // [8192,8192] f32
    const float* ker = (const float*)d_in[1];   // [15,15] f32
    float* out = (float*)d_out;                 // [8192,8192] f32
    (void)in_sizes; (void)n_in; (void)out_size;

    prep_kernel<<<1, 32>>>(ker);

    dim3 grid(IMG_W / TILE_W, IMG_H / TILE_H);  // 32 x 128
    gauss_kernel<<<grid, TPB, SMEM_BYTES>>>(img, out);
}

// round 11
// speedup vs baseline: 1.7134x; 1.3030x over previous
#include <cuda_runtime.h>
#include <cstdint>

// Gaussian 15x15 separable blur, 8192x8192 fp32, reflect pad, stride 1.
// 15-row cp.async groups (2 in flight) into a 30-row smem ring; horizontal
// conv 2 cols/thread with scalar-even / packed-odd symmetric decomposition;
// vertical conv via 15-slot f32x2 register accumulator ring.
// All smem-slot / acc-slot indices are compile-time immediates.
// R10: launch_bounds(128,6) for scheduling headroom + division-free prefetch.

#define IMG_W 8192
#define IMG_H 8192
#define KS 15
#define HALO 7
#define TPB 128
#define TILE_W 256
#define TILE_H 64
#define NROWS (TILE_H + 2*HALO)     // 78 input rows per strip
#define ROW_F 272                   // floats per buffered row (x0-8 .. x0+263)
#define ROW_U (ROW_F/2)             // 136 ull per row
#define RING 30                     // 2 x 15-row groups
#define SMEM_BYTES (RING * ROW_F * 4)   // 32640 B

typedef unsigned long long ull;

static __device__ float g_k[KS];    // 1D Gaussian (kx == ky, sigma equal)

__device__ __forceinline__ int reflect_idx(int p, int n) {
    p = (p < 0) ? -p : p;
    p = (p >= n) ? (2*n - 2 - p) : p;
    return p;
}
__device__ __forceinline__ ull pk2(float lo, float hi) {
    ull r; asm("mov.b64 %0, {%1, %2};" : "=l"(r) : "f"(lo), "f"(hi)); return r;
}
__device__ __forceinline__ void upk2(ull v, float& lo, float& hi) {
    asm("mov.b64 {%0, %1}, %2;" : "=f"(lo), "=f"(hi) : "l"(v));
}
__device__ __forceinline__ ull ffma2(ull a, ull b, ull c) {
    ull d; asm("fma.rn.f32x2 %0, %1, %2, %3;" : "=l"(d) : "l"(a), "l"(b), "l"(c)); return d;
}
__device__ __forceinline__ ull add2(ull a, ull b) {
    ull d; asm("add.rn.f32x2 %0, %1, %2;" : "=l"(d) : "l"(a), "l"(b)); return d;
}
__device__ __forceinline__ ull mul2(ull a, ull b) {
    ull d; asm("mul.rn.f32x2 %0, %1, %2;" : "=l"(d) : "l"(a), "l"(b)); return d;
}
__device__ __forceinline__ void cp16(uint32_t saddr, const float* g) {
    asm volatile("cp.async.cg.shared.global [%0], [%1], 16;"
                 :: "r"(saddr), "l"(g) : "memory");
}
#define CP_COMMIT() asm volatile("cp.async.commit_group;" ::: "memory")
#define CP_WAIT(N)  asm volatile("cp.async.wait_group %0;" :: "n"(N) : "memory")

// 1D kernel from the outer-product 2D kernel: row t sums to ky[t].
__global__ void prep_kernel(const float* __restrict__ k2d) {
    int t = threadIdx.x;
    if (t < KS) {
        float s = 0.f;
#pragma unroll
        for (int i = 0; i < KS; i++) s += k2d[t * KS + i];
        g_k[t] = s;
    }
}

// One input row in ring slot SLOT (compile-time), AMOD = r mod 15:
// horizontal conv for this thread's 2 cols, vertical accumulate into the
// 15-slot acc ring; optionally emit output row r-14.
//   odd taps : packed f32x2 on aligned smem pairs (symmetric)
//   even taps: scalar symmetric sums on pair lanes (free extraction)
template<int SLOT, int AMOD, int DMAX, bool EMIT>
__device__ __forceinline__ void rstep(const ull* __restrict__ wb,
                                      ull* acc, const ull* k2, float* op) {
    const ull* w = wb + SLOT * ROW_U;       // immediate offset
    ull P0 = w[0], P1 = w[1], P2 = w[2], P3 = w[3], P4 = w[4],
        P5 = w[5], P6 = w[6], P7 = w[7], P8 = w[8];
    float lo0, hi0, lo1, hi1, lo2, hi2, lo3, hi3, lo4, hi4,
          lo5, hi5, lo6, hi6, lo7, hi7, lo8, hi8;
    upk2(P0, lo0, hi0); upk2(P1, lo1, hi1); upk2(P2, lo2, hi2);
    upk2(P3, lo3, hi3); upk2(P4, lo4, hi4); upk2(P5, lo5, hi5);
    upk2(P6, lo6, hi6); upk2(P7, lo7, hi7); upk2(P8, lo8, hi8);

    // packed odd taps (coeffs k1,k3,k5,k7)
    ull s1 = add2(P1, P7);
    ull s2 = add2(P2, P6);
    ull s3 = add2(P3, P5);
    ull c1 = ffma2(k2[3], s2, mul2(k2[1], s1));
    ull c2 = ffma2(k2[5], s3, mul2(k2[7], P4));
    ull hod = add2(c1, c2);

    // scalar even taps (coeffs k0,k2,k4,k6)
    float k0s, k2s, k4s, k6s, dump;
    upk2(k2[0], k0s, dump); upk2(k2[2], k2s, dump);
    upk2(k2[4], k4s, dump); upk2(k2[6], k6s, dump);
    float t0 = hi0 + hi7, t1 = hi1 + hi6, t2 = hi2 + hi5, t3 = hi3 + hi4;
    float e0 = fmaf(k2s, t1, k0s * t0) + fmaf(k6s, t3, k4s * t2);
    float u0 = lo1 + lo8, u1 = lo2 + lo7, u2 = lo3 + lo6, u3 = lo4 + lo5;
    float e1 = fmaf(k2s, u1, k0s * u0) + fmaf(k6s, u3, k4s * u2);

    ull h = add2(hod, pk2(e0, e1));

    // vertical: row r feeds outputs t = r-d, d = 0..DMAX, coeff k[min(d,14-d)]
#pragma unroll
    for (int d = 0; d <= DMAX; d++) {
        const int s = ((AMOD - d) % 15 + 15) % 15;
        const int ci = (d < 8) ? d : 14 - d;
        acc[s] = ffma2(k2[ci], h, acc[s]);
    }
    if (EMIT) {
        constexpr int st = (AMOD + 1) % 15;     // slot of output row r-14
        float o0, o1; upk2(acc[st], o0, o1);
        *(float2*)op = make_float2(o0, o1);
        acc[st] = 0ull;
    }
}

// Async prefetch of a 15-row group at input row `base` into ring slots
// sbase..sbase+14. Warp w handles rows w, w+4, ... (division-free);
// lanes cover 68 float4 per row. Always commits.
__device__ __forceinline__ void prefetch15(uint32_t ring_s, float* ring_g,
                                           const float* in, int x0, int y0,
                                           int base, int sbase,
                                           bool xb, int tid) {
    if (base < NROWS) {
        int nr = NROWS - base; if (nr > 15) nr = 15;
        const int wrp = tid >> 5, lane = tid & 31;
        if (!xb) {
#pragma unroll 1
            for (int rr = wrp; rr < nr; rr += 4) {
                int gy = reflect_idx(y0 - HALO + base + rr, IMG_H);
                const float* src = in + (size_t)gy * IMG_W + (x0 - 8);
                uint32_t dst = ring_s + (uint32_t)((sbase + rr) * ROW_F * 4);
                cp16(dst + lane * 16,        src + lane * 4);
                cp16(dst + (lane + 32) * 16, src + (lane + 32) * 4);
                if (lane < 4)
                    cp16(dst + (lane + 64) * 16, src + (lane + 64) * 4);
            }
        } else {
#pragma unroll 1
            for (int rr = wrp; rr < nr; rr += 4) {
                int gy = reflect_idx(y0 - HALO + base + rr, IMG_H);
                const float* row = in + (size_t)gy * IMG_W;
                float* dst = ring_g + (sbase + rr) * ROW_F;
                for (int i = lane; i < ROW_F; i += 32)
                    dst[i] = __ldg(row + reflect_idx(x0 - 8 + i, IMG_W));
            }
        }
    }
    CP_COMMIT();
}

extern __shared__ float ring[];

__global__ void __launch_bounds__(TPB, 6)
gauss_kernel(const float* __restrict__ in, float* __restrict__ out) {
    const int tid = threadIdx.x;
    const int x0 = blockIdx.x * TILE_W;
    const int y0 = blockIdx.y * TILE_H;
    const bool xb = (blockIdx.x == 0) || (blockIdx.x == gridDim.x - 1);
    const uint32_t ring_s = (uint32_t)__cvta_generic_to_shared(ring);
    const ull* wb = (const ull*)ring + tid;          // thread's first tap pair

    ull k2[8];
#pragma unroll
    for (int i = 0; i < 8; i++) { float a = g_k[i]; k2[i] = pk2(a, a); }
    ull acc[15];
#pragma unroll
    for (int i = 0; i < 15; i++) acc[i] = 0ull;

    float* outx = out + (size_t)y0 * IMG_W + x0 + 2 * tid;
    const size_t W = IMG_W;

    // Prime: g0 (rows 0-14 -> slots 0-14), g1 (rows 15-29 -> slots 15-29).
    prefetch15(ring_s, ring, in, x0, y0,  0,  0, xb, tid);
    prefetch15(ring_s, ring, in, x0, y0, 15, 15, xb, tid);

    // Full steady block: 15 rows at slot base SB (0 or 15), every row emits.
#define PH(SB, ob) \
    rstep<(SB)+ 0, 0,14,true>(wb, acc, k2, (ob) +  0*W); \
    rstep<(SB)+ 1, 1,14,true>(wb, acc, k2, (ob) +  1*W); \
    rstep<(SB)+ 2, 2,14,true>(wb, acc, k2, (ob) +  2*W); \
    rstep<(SB)+ 3, 3,14,true>(wb, acc, k2, (ob) +  3*W); \
    rstep<(SB)+ 4, 4,14,true>(wb, acc, k2, (ob) +  4*W); \
    rstep<(SB)+ 5, 5,14,true>(wb, acc, k2, (ob) +  5*W); \
    rstep<(SB)+ 6, 6,14,true>(wb, acc, k2, (ob) +  6*W); \
    rstep<(SB)+ 7, 7,14,true>(wb, acc, k2, (ob) +  7*W); \
    rstep<(SB)+ 8, 8,14,true>(wb, acc, k2, (ob) +  8*W); \
    rstep<(SB)+ 9, 9,14,true>(wb, acc, k2, (ob) +  9*W); \
    rstep<(SB)+10,10,14,true>(wb, acc, k2, (ob) + 10*W); \
    rstep<(SB)+11,11,14,true>(wb, acc, k2, (ob) + 11*W); \
    rstep<(SB)+12,12,14,true>(wb, acc, k2, (ob) + 12*W); \
    rstep<(SB)+13,13,14,true>(wb, acc, k2, (ob) + 13*W); \
    rstep<(SB)+14,14,14,true>(wb, acc, k2, (ob) + 14*W);

    // ---- B0: rows 0..14 (warmup; row 14 emits output 0) ----
    CP_WAIT(1); __syncthreads();
    rstep< 0, 0, 0,false>(wb, acc, k2, outx);
    rstep< 1, 1, 1,false>(wb, acc, k2, outx);
    rstep< 2, 2, 2,false>(wb, acc, k2, outx);
    rstep< 3, 3, 3,false>(wb, acc, k2, outx);
    rstep< 4, 4, 4,false>(wb, acc, k2, outx);
    rstep< 5, 5, 5,false>(wb, acc, k2, outx);
    rstep< 6, 6, 6,false>(wb, acc, k2, outx);
    rstep< 7, 7, 7,false>(wb, acc, k2, outx);
    rstep< 8, 8, 8,false>(wb, acc, k2, outx);
    rstep< 9, 9, 9,false>(wb, acc, k2, outx);
    rstep<10,10,10,false>(wb, acc, k2, outx);
    rstep<11,11,11,false>(wb, acc, k2, outx);
    rstep<12,12,12,false>(wb, acc, k2, outx);
    rstep<13,13,13,false>(wb, acc, k2, outx);
    rstep<14,14,14,true >(wb, acc, k2, outx);      // output row 0
    __syncthreads();
    prefetch15(ring_s, ring, in, x0, y0, 30,  0, xb, tid);   // g2 -> slots 0-14

    // ---- B1: rows 15..29 -> outputs 1..15 ----
    CP_WAIT(1); __syncthreads();
    PH(15, outx + (size_t)1 * W)
    __syncthreads();
    prefetch15(ring_s, ring, in, x0, y0, 45, 15, xb, tid);   // g3 -> slots 15-29

    // ---- B2: rows 30..44 -> outputs 16..30 ----
    CP_WAIT(1); __syncthreads();
    PH(0, outx + (size_t)16 * W)
    __syncthreads();
    prefetch15(ring_s, ring, in, x0, y0, 60,  0, xb, tid);   // g4 -> slots 0-14

    // ---- B3: rows 45..59 -> outputs 31..45 ----
    CP_WAIT(1); __syncthreads();
    PH(15, outx + (size_t)31 * W)
    __syncthreads();
    prefetch15(ring_s, ring, in, x0, y0, 75, 15, xb, tid);   // g5 (3 rows) -> 15-17

    // ---- B4: rows 60..74 -> outputs 46..60 ----
    CP_WAIT(1); __syncthreads();
    PH(0, outx + (size_t)46 * W)
    __syncthreads();

    // ---- B5: rows 75..77 -> outputs 61..63 ----
    CP_WAIT(0); __syncthreads();
    rstep<15, 0,14,true>(wb, acc, k2, outx + (size_t)61 * W);
    rstep<16, 1,14,true>(wb, acc, k2, outx + (size_t)62 * W);
    rstep<17, 2,14,true>(wb, acc, k2, outx + (size_t)63 * W);
}

extern "C" void kernel_launch(void* const* d_in, const int* in_sizes, int n_in,
                              void* d_out, int out_size) {
    const float* img = (const float*)d_in[0];   // [8192,8192] f32
    const float* ker = (const float*)d_in[1];   // [15,15] f32
    float* out = (float*)d_out;                 // [8192,8192] f32
    (void)in_sizes; (void)n_in; (void)out_size;

    prep_kernel<<<1, 32>>>(ker);

    dim3 grid(IMG_W / TILE_W, IMG_H / TILE_H);  // 32 x 128
    gauss_kernel<<<grid, TPB, SMEM_BYTES>>>(img, out);
}